// round 2
// baseline (speedup 1.0000x reference)
#include <cuda_runtime.h>
#include <math.h>

#define BB 128
#define NN 64
#define DD 64
#define NT 512

// ---------------- shared memory layout ----------------
struct Smem {
    float H[NN * DD];        // 4096   node features of this batch
    float Q[NN * DD];        // 4096   LN'd per-node Q
    float P[NN * 128];       // 8192   H @ kv_w1[1:,:]
    float W2[128 * 128];     // 16384  staging: q_w1/q_w2/kv_w1/kv_w2/phh
    float PhxW1[DD * DD];    // 4096
    float Kv1[NN * 128];     // 8192   silu'd kv1   (also att[64x64] / M scratch)
    float Kv[NN * 128];      // 8192   kv = K|V     (also t scratch)
    float Xn[NN * 4];
    float Rel[NN * 4];
    float Rd[NN];
    float Score[NN];
    float Alpha[NN];
    float Phx[NN];
    float W1r0[128];
    float PhxW2[DD];
    float QnW[DD], QnB[DD], KnW[DD], KnB[DD];
    float B1[DD], B2[DD];
    float meanNorm;
};

// per-node attention aggregate A (N x D) — scratch, static device global (no runtime alloc)
__device__ float g_A[BB * NN * DD];

__device__ __forceinline__ float wredsum(float v) {
#pragma unroll
    for (int o = 16; o > 0; o >>= 1) v += __shfl_xor_sync(0xffffffffu, v, o);
    return v;
}
__device__ __forceinline__ float wredmax(float v) {
#pragma unroll
    for (int o = 16; o > 0; o >>= 1) v = fmaxf(v, __shfl_xor_sync(0xffffffffu, v, o));
    return v;
}
__device__ __forceinline__ float silu(float x) { return x / (1.f + __expf(-x)); }

__global__ __launch_bounds__(NT, 1)
void se3_kernel(const float* __restrict__ X, const float* __restrict__ Hg,
                const float* __restrict__ xnw,
                const float* __restrict__ q_w1, const float* __restrict__ q_w2,
                const float* __restrict__ kv_w1, const float* __restrict__ kv_w2,
                const float* __restrict__ qn_w, const float* __restrict__ qn_b,
                const float* __restrict__ kn_w, const float* __restrict__ kn_b,
                const float* __restrict__ phx_w1, const float* __restrict__ phx_w2,
                const float* __restrict__ phh_w1, const float* __restrict__ phh_b1,
                const float* __restrict__ phh_w2, const float* __restrict__ phh_b2,
                float* __restrict__ Xout, float* __restrict__ Hout)
{
    extern __shared__ char smem_raw[];
    Smem& s = *reinterpret_cast<Smem*>(smem_raw);

    const int tid  = threadIdx.x;
    const int lane = tid & 31;
    const int wid  = tid >> 5;
    const int nb   = blockIdx.x * NN;   // first node of this batch

    // ---------------- phase 0: per-node precompute ----------------
    for (int i = tid; i < NN * DD; i += NT) s.H[i] = Hg[nb * DD + i];
    if (tid < DD) {
        s.QnW[tid] = qn_w[tid];  s.QnB[tid] = qn_b[tid];
        s.KnW[tid] = kn_w[tid];  s.KnB[tid] = kn_b[tid];
        s.PhxW2[tid] = phx_w2[tid];
        s.B1[tid] = phh_b1[tid]; s.B2[tid] = phh_b2[tid];
    }
    if (tid < NN) {
        float x0 = X[(nb + tid) * 3 + 0];
        float x1 = X[(nb + tid) * 3 + 1];
        float x2 = X[(nb + tid) * 3 + 2];
        s.Rd[tid] = sqrtf(x0 * x0 + x1 * x1 + x2 * x2);   // node norm (temp in Rd)
        s.Xn[tid * 4 + 0] = x0; s.Xn[tid * 4 + 1] = x1; s.Xn[tid * 4 + 2] = x2;
    }
    for (int i = tid; i < DD * DD; i += NT) s.W2[i] = q_w1[i];
    __syncthreads();

    if (tid == 0) {
        float m = 0.f;
        for (int i = 0; i < NN; i++) m += s.Rd[i];
        s.meanNorm = m * (1.f / NN);
    }
    __syncthreads();

    if (tid < NN) {
        float sc = xnw[0] / (s.meanNorm + 1e-5f);
        s.Xn[tid * 4 + 0] *= sc; s.Xn[tid * 4 + 1] *= sc; s.Xn[tid * 4 + 2] *= sc;
    }

    // t1 = silu(H @ q_w1)  -> Kv1 (stride 64)
    {
        int r0 = wid * 4, j0 = lane * 2;
        float acc[4][2] = {};
#pragma unroll 8
        for (int k = 0; k < DD; k++) {
            float2 bv = *(const float2*)&s.W2[k * DD + j0];
#pragma unroll
            for (int i = 0; i < 4; i++) {
                float a = s.H[(r0 + i) * DD + k];
                acc[i][0] += a * bv.x; acc[i][1] += a * bv.y;
            }
        }
#pragma unroll
        for (int i = 0; i < 4; i++) {
            s.Kv1[(r0 + i) * DD + j0 + 0] = silu(acc[i][0]);
            s.Kv1[(r0 + i) * DD + j0 + 1] = silu(acc[i][1]);
        }
    }
    __syncthreads();
    for (int i = tid; i < DD * DD; i += NT) s.W2[i] = q_w2[i];
    __syncthreads();

    // Q0 = t1 @ q_w2 -> Kv (stride 64)
    {
        int r0 = wid * 4, j0 = lane * 2;
        float acc[4][2] = {};
#pragma unroll 8
        for (int k = 0; k < DD; k++) {
            float2 bv = *(const float2*)&s.W2[k * DD + j0];
#pragma unroll
            for (int i = 0; i < 4; i++) {
                float a = s.Kv1[(r0 + i) * DD + k];
                acc[i][0] += a * bv.x; acc[i][1] += a * bv.y;
            }
        }
#pragma unroll
        for (int i = 0; i < 4; i++) {
            s.Kv[(r0 + i) * DD + j0 + 0] = acc[i][0];
            s.Kv[(r0 + i) * DD + j0 + 1] = acc[i][1];
        }
    }
    __syncthreads();

    // LN(Q0) -> Q ; concurrently stage kv_w1 into W2
#pragma unroll
    for (int i = 0; i < 4; i++) {
        int r = wid * 4 + i;
        float v0 = s.Kv[r * DD + lane], v1 = s.Kv[r * DD + 32 + lane];
        float sum = wredsum(v0 + v1);
        float sq  = wredsum(v0 * v0 + v1 * v1);
        float mu  = sum * (1.f / DD);
        float var = sq * (1.f / DD) - mu * mu;
        float rstd = rsqrtf(var + 1e-5f);
        s.Q[r * DD + lane]      = (v0 - mu) * rstd * s.QnW[lane]      + s.QnB[lane];
        s.Q[r * DD + 32 + lane] = (v1 - mu) * rstd * s.QnW[lane + 32] + s.QnB[lane + 32];
    }
    for (int i = tid; i < 65 * 128; i += NT) s.W2[i] = kv_w1[i];
    __syncthreads();

    // P = H @ kv_w1[1:,:]   (64 x 128)
    {
        int r0 = wid * 4, c0 = lane * 4;
        float acc[4][4] = {};
#pragma unroll 8
        for (int k = 0; k < DD; k++) {
            float4 bv = *(const float4*)&s.W2[(1 + k) * 128 + c0];
#pragma unroll
            for (int i = 0; i < 4; i++) {
                float a = s.H[(r0 + i) * DD + k];
                acc[i][0] += a * bv.x; acc[i][1] += a * bv.y;
                acc[i][2] += a * bv.z; acc[i][3] += a * bv.w;
            }
        }
#pragma unroll
        for (int i = 0; i < 4; i++)
            *(float4*)&s.P[(r0 + i) * 128 + c0] =
                make_float4(acc[i][0], acc[i][1], acc[i][2], acc[i][3]);
    }
    if (tid < 128) s.W1r0[tid] = s.W2[tid];   // kv_w1 row 0 (rel_dist weights)
    __syncthreads();

    for (int i = tid; i < 128 * 128; i += NT) s.W2[i] = kv_w2[i];
    for (int i = tid; i < DD * DD; i += NT) s.PhxW1[i] = phx_w1[i];
    __syncthreads();

    // ---------------- main loop over dst nodes ----------------
    for (int d = 0; d < NN; d++) {
        // rel / rel_dist
        if (tid < NN) {
            float r0v = s.Xn[tid * 4 + 0] - s.Xn[d * 4 + 0];
            float r1v = s.Xn[tid * 4 + 1] - s.Xn[d * 4 + 1];
            float r2v = s.Xn[tid * 4 + 2] - s.Xn[d * 4 + 2];
            s.Rel[tid * 4 + 0] = r0v; s.Rel[tid * 4 + 1] = r1v; s.Rel[tid * 4 + 2] = r2v;
            s.Rd[tid] = r0v * r0v + r1v * r1v + r2v * r2v;
        }
        __syncthreads();

        // kv1 = silu(rd * w1row0 + P)
        for (int i = tid; i < NN * 128; i += NT) {
            int e = i >> 7, c = i & 127;
            float x = s.Rd[e] * s.W1r0[c] + s.P[i];
            s.Kv1[i] = silu(x);
        }
        __syncthreads();

        // GEMM1: kv = kv1 @ kv_w2   (64 x 128 x 128)
        {
            int r0 = wid * 4, c0 = lane * 4;
            float acc[4][4] = {};
#pragma unroll 8
            for (int k = 0; k < 128; k++) {
                float4 bv = *(const float4*)&s.W2[k * 128 + c0];
#pragma unroll
                for (int i = 0; i < 4; i++) {
                    float a = s.Kv1[(r0 + i) * 128 + k];
                    acc[i][0] += a * bv.x; acc[i][1] += a * bv.y;
                    acc[i][2] += a * bv.z; acc[i][3] += a * bv.w;
                }
            }
#pragma unroll
            for (int i = 0; i < 4; i++)
                *(float4*)&s.Kv[(r0 + i) * 128 + c0] =
                    make_float4(acc[i][0], acc[i][1], acc[i][2], acc[i][3]);
        }
        __syncthreads();

        // LN(K) + score, warp per edge
#pragma unroll
        for (int i = 0; i < 4; i++) {
            int e = wid * 4 + i;
            float k0 = s.Kv[e * 128 + lane], k1 = s.Kv[e * 128 + 32 + lane];
            float sum = wredsum(k0 + k1);
            float sq  = wredsum(k0 * k0 + k1 * k1);
            float mu  = sum * (1.f / DD);
            float var = sq * (1.f / DD) - mu * mu;
            float rstd = rsqrtf(var + 1e-5f);
            float kh0 = (k0 - mu) * rstd * s.KnW[lane]      + s.KnB[lane];
            float kh1 = (k1 - mu) * rstd * s.KnW[lane + 32] + s.KnB[lane + 32];
            float dot = wredsum(kh0 * s.Q[d * DD + lane] + kh1 * s.Q[d * DD + 32 + lane]);
            if (lane == 0) s.Score[e] = dot * 0.125f;   // / sqrt(64)
        }
        __syncthreads();

        // softmax over incoming edges (mask self)
        if (wid == 0) {
            float s0 = s.Score[lane], s1 = s.Score[lane + 32];
            if (lane == d)      s0 = -1e30f;
            if (lane + 32 == d) s1 = -1e30f;
            float m  = wredmax(fmaxf(s0, s1));
            float e0 = __expf(s0 - m), e1 = __expf(s1 - m);
            float ss = wredsum(e0 + e1);
            float inv = 1.f / ss;
            s.Alpha[lane]      = e0 * inv;
            s.Alpha[lane + 32] = e1 * inv;
        }
        __syncthreads();

        // att = alpha * V  (into Kv1, stride 64) ; A[d] -> g_A
        for (int i = tid; i < NN * DD; i += NT) {
            int e = i >> 6, c = i & 63;
            s.Kv1[i] = s.Alpha[e] * s.Kv[e * 128 + 64 + c];
        }
        if (tid < DD) {
            float a = 0.f;
            for (int e = 0; e < NN; e++) a += s.Alpha[e] * s.Kv[e * 128 + 64 + tid];
            g_A[(nb + d) * DD + tid] = a;
        }
        __syncthreads();

        // GEMM2: t = silu(att @ phx_w1) ; phx[e] = t . phx_w2
        {
            int r0 = wid * 4, j0 = lane * 2;
            float acc[4][2] = {};
#pragma unroll 8
            for (int k = 0; k < DD; k++) {
                float2 bv = *(const float2*)&s.PhxW1[k * DD + j0];
#pragma unroll
                for (int i = 0; i < 4; i++) {
                    float a = s.Kv1[(r0 + i) * DD + k];
                    acc[i][0] += a * bv.x; acc[i][1] += a * bv.y;
                }
            }
            float w0 = s.PhxW2[j0], w1 = s.PhxW2[j0 + 1];
#pragma unroll
            for (int i = 0; i < 4; i++) {
                float p = wredsum(silu(acc[i][0]) * w0 + silu(acc[i][1]) * w1);
                if (lane == 0) s.Phx[r0 + i] = p;
            }
        }
        __syncthreads();

        // X_out[d] = Xn[d] + sum_e X_rel_norm[e] * phx[e]
        if (wid == 0) {
            float p0 = 0.f, p1 = 0.f, p2 = 0.f;
#pragma unroll
            for (int t2 = 0; t2 < 2; t2++) {
                int e = lane + 32 * t2;
                float w = s.Phx[e] / (1.f + sqrtf(s.Rd[e] + 1e-8f));
                p0 += s.Rel[e * 4 + 0] * w;
                p1 += s.Rel[e * 4 + 1] * w;
                p2 += s.Rel[e * 4 + 2] * w;
            }
            p0 = wredsum(p0); p1 = wredsum(p1); p2 = wredsum(p2);
            if (lane == 0) {
                Xout[(nb + d) * 3 + 0] = s.Xn[d * 4 + 0] + p0;
                Xout[(nb + d) * 3 + 1] = s.Xn[d * 4 + 1] + p1;
                Xout[(nb + d) * 3 + 2] = s.Xn[d * 4 + 2] + p2;
            }
        }
        __syncthreads();
    }

    // ---------------- phase 2: H_out ----------------
    for (int i = tid; i < DD * DD; i += NT) s.W2[i]        = phh_w1[i];
    for (int i = tid; i < DD * DD; i += NT) s.W2[4096 + i] = phh_w2[i];
    __syncthreads();

    // M = A^2 * H  (A*AH with AH = A*H[dst])
    for (int i = tid; i < NN * DD; i += NT) {
        float a = g_A[nb * DD + i];
        s.Kv1[i] = a * a * s.H[i];
    }
    __syncthreads();

    // t = silu(M @ phh_w1 + b1) -> Kv (stride 64)
    {
        int r0 = wid * 4, j0 = lane * 2;
        float acc[4][2] = {};
#pragma unroll 8
        for (int k = 0; k < DD; k++) {
            float2 bv = *(const float2*)&s.W2[k * DD + j0];
#pragma unroll
            for (int i = 0; i < 4; i++) {
                float a = s.Kv1[(r0 + i) * DD + k];
                acc[i][0] += a * bv.x; acc[i][1] += a * bv.y;
            }
        }
#pragma unroll
        for (int i = 0; i < 4; i++) {
            s.Kv[(r0 + i) * DD + j0 + 0] = silu(acc[i][0] + s.B1[j0 + 0]);
            s.Kv[(r0 + i) * DD + j0 + 1] = silu(acc[i][1] + s.B1[j0 + 1]);
        }
    }
    __syncthreads();

    // H_out = H + t @ phh_w2 + b2
    {
        int r0 = wid * 4, j0 = lane * 2;
        float acc[4][2] = {};
#pragma unroll 8
        for (int k = 0; k < DD; k++) {
            float2 bv = *(const float2*)&s.W2[4096 + k * DD + j0];
#pragma unroll
            for (int i = 0; i < 4; i++) {
                float a = s.Kv[(r0 + i) * DD + k];
                acc[i][0] += a * bv.x; acc[i][1] += a * bv.y;
            }
        }
#pragma unroll
        for (int i = 0; i < 4; i++) {
            int n = r0 + i;
            Hout[(nb + n) * DD + j0 + 0] = s.H[n * DD + j0 + 0] + acc[i][0] + s.B2[j0 + 0];
            Hout[(nb + n) * DD + j0 + 1] = s.H[n * DD + j0 + 1] + acc[i][1] + s.B2[j0 + 1];
        }
    }
}

extern "C" void kernel_launch(void* const* d_in, const int* in_sizes, int n_in,
                              void* d_out, int out_size)
{
    // metadata order:
    // 0 batch, 1 X, 2 H, 3 E_idx, 4 x_norm_w, 5 q_w1, 6 q_w2, 7 kv_w1, 8 kv_w2,
    // 9 qn_w, 10 qn_b, 11 kn_w, 12 kn_b, 13 phx_w1, 14 phx_w2,
    // 15 phh_w1, 16 phh_b1, 17 phh_w2, 18 phh_b2
    const float* X      = (const float*)d_in[1];
    const float* Hg     = (const float*)d_in[2];
    const float* xnw    = (const float*)d_in[4];
    const float* q_w1   = (const float*)d_in[5];
    const float* q_w2   = (const float*)d_in[6];
    const float* kv_w1  = (const float*)d_in[7];
    const float* kv_w2  = (const float*)d_in[8];
    const float* qn_w   = (const float*)d_in[9];
    const float* qn_b   = (const float*)d_in[10];
    const float* kn_w   = (const float*)d_in[11];
    const float* kn_b   = (const float*)d_in[12];
    const float* phx_w1 = (const float*)d_in[13];
    const float* phx_w2 = (const float*)d_in[14];
    const float* phh_w1 = (const float*)d_in[15];
    const float* phh_b1 = (const float*)d_in[16];
    const float* phh_w2 = (const float*)d_in[17];
    const float* phh_b2 = (const float*)d_in[18];

    float* out  = (float*)d_out;
    float* Xout = out;                      // (N, 3) first
    float* Hout = out + BB * NN * 3;        // (N, 64) second

    cudaFuncSetAttribute(se3_kernel, cudaFuncAttributeMaxDynamicSharedMemorySize,
                         (int)sizeof(Smem));

    se3_kernel<<<BB, NT, sizeof(Smem)>>>(X, Hg, xnw, q_w1, q_w2, kv_w1, kv_w2,
                                         qn_w, qn_b, kn_w, kn_b,
                                         phx_w1, phx_w2,
                                         phh_w1, phh_b1, phh_w2, phh_b2,
                                         Xout, Hout);
}

// round 3
// speedup vs baseline: 1.0860x; 1.0860x over previous
#include <cuda_runtime.h>
#include <math.h>

#define BB 128
#define NN 64
#define DD 64
#define NT 512

typedef unsigned long long u64;

// ---------------- shared memory layout ----------------
struct Smem {
    float H[NN * DD];        // 16KB  node features of this batch
    float Q[NN * DD];        // 16KB  LN'd per-node Q
    float P[NN * 128];       // 32KB  H @ kv_w1[1:,:]
    float W2[128 * 128];     // 64KB  staging: q_w1/q_w2/kv_w1/kv_w2/phh
    float PhxW1[DD * DD];    // 16KB
    float Kv1[NN * 128];     // 32KB  silu'd kv1 (also att / M scratch)
    float Kv[NN * 128];      // 32KB  kv = K|V  (also t scratch)
    float Xn[NN * 4];
    float Rel[NN * 4];
    float Rd[NN];
    float Score[NN];
    float Alpha[NN];
    float Phx[NN];
    float W1r0[128];
    float PhxW2[DD];
    float QnW[DD], QnB[DD], KnW[DD], KnB[DD];
    float B1[DD], B2[DD];
    float meanNorm;
};

// per-node attention aggregate A (N x D) — static device scratch
__device__ float g_A[BB * NN * DD];

__device__ __forceinline__ float wredsum(float v) {
#pragma unroll
    for (int o = 16; o > 0; o >>= 1) v += __shfl_xor_sync(0xffffffffu, v, o);
    return v;
}
__device__ __forceinline__ float wredmax(float v) {
#pragma unroll
    for (int o = 16; o > 0; o >>= 1) v = fmaxf(v, __shfl_xor_sync(0xffffffffu, v, o));
    return v;
}
__device__ __forceinline__ float silu(float x) { return x / (1.f + __expf(-x)); }

// ---- packed fp32x2 helpers (Blackwell FFMA2) ----
__device__ __forceinline__ void fma2(u64& d, u64 a, u64 b) {
    asm("fma.rn.f32x2 %0, %1, %2, %0;" : "+l"(d) : "l"(a), "l"(b));
}
__device__ __forceinline__ u64 dup2(float x) {
    u64 r; asm("mov.b64 %0, {%1, %1};" : "=l"(r) : "f"(x)); return r;
}
__device__ __forceinline__ float2 unpk(u64 v) {
    float2 r; asm("mov.b64 {%0, %1}, %2;" : "=f"(r.x), "=f"(r.y) : "l"(v)); return r;
}

__global__ __launch_bounds__(NT, 1)
void se3_kernel(const float* __restrict__ X, const float* __restrict__ Hg,
                const float* __restrict__ xnw,
                const float* __restrict__ q_w1, const float* __restrict__ q_w2,
                const float* __restrict__ kv_w1, const float* __restrict__ kv_w2,
                const float* __restrict__ qn_w, const float* __restrict__ qn_b,
                const float* __restrict__ kn_w, const float* __restrict__ kn_b,
                const float* __restrict__ phx_w1, const float* __restrict__ phx_w2,
                const float* __restrict__ phh_w1, const float* __restrict__ phh_b1,
                const float* __restrict__ phh_w2, const float* __restrict__ phh_b2,
                float* __restrict__ Xout, float* __restrict__ Hout)
{
    extern __shared__ char smem_raw[];
    Smem& s = *reinterpret_cast<Smem*>(smem_raw);

    const int tid  = threadIdx.x;
    const int lane = tid & 31;
    const int wid  = tid >> 5;
    const int nb   = blockIdx.x * NN;

    // ---------------- phase 0: per-node precompute ----------------
    for (int i = tid; i < NN * DD; i += NT) s.H[i] = Hg[nb * DD + i];
    if (tid < DD) {
        s.QnW[tid] = qn_w[tid];  s.QnB[tid] = qn_b[tid];
        s.KnW[tid] = kn_w[tid];  s.KnB[tid] = kn_b[tid];
        s.PhxW2[tid] = phx_w2[tid];
        s.B1[tid] = phh_b1[tid]; s.B2[tid] = phh_b2[tid];
    }
    if (tid < NN) {
        float x0 = X[(nb + tid) * 3 + 0];
        float x1 = X[(nb + tid) * 3 + 1];
        float x2 = X[(nb + tid) * 3 + 2];
        s.Rd[tid] = sqrtf(x0 * x0 + x1 * x1 + x2 * x2);
        s.Xn[tid * 4 + 0] = x0; s.Xn[tid * 4 + 1] = x1; s.Xn[tid * 4 + 2] = x2;
    }
    for (int i = tid; i < DD * DD; i += NT) s.W2[i] = q_w1[i];
    __syncthreads();

    if (tid == 0) {
        float m = 0.f;
        for (int i = 0; i < NN; i++) m += s.Rd[i];
        s.meanNorm = m * (1.f / NN);
    }
    __syncthreads();

    if (tid < NN) {
        float sc = xnw[0] / (s.meanNorm + 1e-5f);
        s.Xn[tid * 4 + 0] *= sc; s.Xn[tid * 4 + 1] *= sc; s.Xn[tid * 4 + 2] *= sc;
    }

    // t1 = silu(H @ q_w1) -> Kv1 (stride 64)
    {
        int r0 = wid * 4, j0 = lane * 2;
        float acc[4][2] = {};
#pragma unroll 8
        for (int k = 0; k < DD; k++) {
            float2 bv = *(const float2*)&s.W2[k * DD + j0];
#pragma unroll
            for (int i = 0; i < 4; i++) {
                float a = s.H[(r0 + i) * DD + k];
                acc[i][0] += a * bv.x; acc[i][1] += a * bv.y;
            }
        }
#pragma unroll
        for (int i = 0; i < 4; i++) {
            s.Kv1[(r0 + i) * DD + j0 + 0] = silu(acc[i][0]);
            s.Kv1[(r0 + i) * DD + j0 + 1] = silu(acc[i][1]);
        }
    }
    __syncthreads();
    for (int i = tid; i < DD * DD; i += NT) s.W2[i] = q_w2[i];
    __syncthreads();

    // Q0 = t1 @ q_w2 -> Kv (stride 64)
    {
        int r0 = wid * 4, j0 = lane * 2;
        float acc[4][2] = {};
#pragma unroll 8
        for (int k = 0; k < DD; k++) {
            float2 bv = *(const float2*)&s.W2[k * DD + j0];
#pragma unroll
            for (int i = 0; i < 4; i++) {
                float a = s.Kv1[(r0 + i) * DD + k];
                acc[i][0] += a * bv.x; acc[i][1] += a * bv.y;
            }
        }
#pragma unroll
        for (int i = 0; i < 4; i++) {
            s.Kv[(r0 + i) * DD + j0 + 0] = acc[i][0];
            s.Kv[(r0 + i) * DD + j0 + 1] = acc[i][1];
        }
    }
    __syncthreads();

    // LN(Q0) -> Q ; stage kv_w1 into W2
#pragma unroll
    for (int i = 0; i < 4; i++) {
        int r = wid * 4 + i;
        float v0 = s.Kv[r * DD + lane], v1 = s.Kv[r * DD + 32 + lane];
        float sum = wredsum(v0 + v1);
        float sq  = wredsum(v0 * v0 + v1 * v1);
        float mu  = sum * (1.f / DD);
        float var = sq * (1.f / DD) - mu * mu;
        float rstd = rsqrtf(var + 1e-5f);
        s.Q[r * DD + lane]      = (v0 - mu) * rstd * s.QnW[lane]      + s.QnB[lane];
        s.Q[r * DD + 32 + lane] = (v1 - mu) * rstd * s.QnW[lane + 32] + s.QnB[lane + 32];
    }
    for (int i = tid; i < 65 * 128; i += NT) s.W2[i] = kv_w1[i];
    __syncthreads();

    // P = H @ kv_w1[1:,:]  (64 x 128)
    {
        int r0 = wid * 4, c0 = lane * 4;
        float acc[4][4] = {};
#pragma unroll 8
        for (int k = 0; k < DD; k++) {
            float4 bv = *(const float4*)&s.W2[(1 + k) * 128 + c0];
#pragma unroll
            for (int i = 0; i < 4; i++) {
                float a = s.H[(r0 + i) * DD + k];
                acc[i][0] += a * bv.x; acc[i][1] += a * bv.y;
                acc[i][2] += a * bv.z; acc[i][3] += a * bv.w;
            }
        }
#pragma unroll
        for (int i = 0; i < 4; i++)
            *(float4*)&s.P[(r0 + i) * 128 + c0] =
                make_float4(acc[i][0], acc[i][1], acc[i][2], acc[i][3]);
    }
    if (tid < 128) s.W1r0[tid] = s.W2[tid];
    __syncthreads();

    for (int i = tid; i < 128 * 128; i += NT) s.W2[i] = kv_w2[i];
    for (int i = tid; i < DD * DD; i += NT) s.PhxW1[i] = phx_w1[i];
    __syncthreads();

    // ---------------- main loop over dst nodes ----------------
    for (int d = 0; d < NN; d++) {
        // rel / rel_dist
        if (tid < NN) {
            float r0v = s.Xn[tid * 4 + 0] - s.Xn[d * 4 + 0];
            float r1v = s.Xn[tid * 4 + 1] - s.Xn[d * 4 + 1];
            float r2v = s.Xn[tid * 4 + 2] - s.Xn[d * 4 + 2];
            s.Rel[tid * 4 + 0] = r0v; s.Rel[tid * 4 + 1] = r1v; s.Rel[tid * 4 + 2] = r2v;
            s.Rd[tid] = r0v * r0v + r1v * r1v + r2v * r2v;
        }
        __syncthreads();

        // kv1 = silu(rd * w1row0 + P)   (vectorized)
        for (int i = tid * 4; i < NN * 128; i += NT * 4) {
            int e = i >> 7;
            float rd = s.Rd[e];
            float4 p = *(const float4*)&s.P[i];
            float4 w = *(const float4*)&s.W1r0[i & 127];
            float4 o;
            o.x = silu(fmaf(rd, w.x, p.x));
            o.y = silu(fmaf(rd, w.y, p.y));
            o.z = silu(fmaf(rd, w.z, p.z));
            o.w = silu(fmaf(rd, w.w, p.w));
            *(float4*)&s.Kv1[i] = o;
        }
        __syncthreads();

        // GEMM1: kv = kv1 @ kv_w2  (64 x 128 x 128) — packed f32x2
        {
            const int r0 = wid * 4, c0 = lane * 4;
            u64 acc[4][2] = {};
#pragma unroll 4
            for (int k4 = 0; k4 < 128; k4 += 4) {
                float4 a0 = *(const float4*)&s.Kv1[(r0 + 0) * 128 + k4];
                float4 a1 = *(const float4*)&s.Kv1[(r0 + 1) * 128 + k4];
                float4 a2 = *(const float4*)&s.Kv1[(r0 + 2) * 128 + k4];
                float4 a3 = *(const float4*)&s.Kv1[(r0 + 3) * 128 + k4];
                const float* f0 = &a0.x; const float* f1 = &a1.x;
                const float* f2 = &a2.x; const float* f3 = &a3.x;
#pragma unroll
                for (int kk = 0; kk < 4; kk++) {
                    u64 b01 = *(const u64*)&s.W2[(k4 + kk) * 128 + c0];
                    u64 b23 = *(const u64*)&s.W2[(k4 + kk) * 128 + c0 + 2];
                    u64 d0 = dup2(f0[kk]);
                    u64 d1 = dup2(f1[kk]);
                    u64 d2 = dup2(f2[kk]);
                    u64 d3 = dup2(f3[kk]);
                    fma2(acc[0][0], d0, b01); fma2(acc[0][1], d0, b23);
                    fma2(acc[1][0], d1, b01); fma2(acc[1][1], d1, b23);
                    fma2(acc[2][0], d2, b01); fma2(acc[2][1], d2, b23);
                    fma2(acc[3][0], d3, b01); fma2(acc[3][1], d3, b23);
                }
            }
#pragma unroll
            for (int i = 0; i < 4; i++) {
                float2 lo = unpk(acc[i][0]);
                float2 hi = unpk(acc[i][1]);
                *(float4*)&s.Kv[(r0 + i) * 128 + c0] = make_float4(lo.x, lo.y, hi.x, hi.y);
            }
        }
        __syncthreads();

        // LN(K) + score, warp per edge
#pragma unroll
        for (int i = 0; i < 4; i++) {
            int e = wid * 4 + i;
            float k0 = s.Kv[e * 128 + lane], k1 = s.Kv[e * 128 + 32 + lane];
            float sum = wredsum(k0 + k1);
            float sq  = wredsum(k0 * k0 + k1 * k1);
            float mu  = sum * (1.f / DD);
            float var = sq * (1.f / DD) - mu * mu;
            float rstd = rsqrtf(var + 1e-5f);
            float kh0 = (k0 - mu) * rstd * s.KnW[lane]      + s.KnB[lane];
            float kh1 = (k1 - mu) * rstd * s.KnW[lane + 32] + s.KnB[lane + 32];
            float dot = wredsum(kh0 * s.Q[d * DD + lane] + kh1 * s.Q[d * DD + 32 + lane]);
            if (lane == 0) s.Score[e] = dot * 0.125f;
        }
        __syncthreads();

        // softmax over incoming edges (mask self)
        if (wid == 0) {
            float s0 = s.Score[lane], s1 = s.Score[lane + 32];
            if (lane == d)      s0 = -1e30f;
            if (lane + 32 == d) s1 = -1e30f;
            float m  = wredmax(fmaxf(s0, s1));
            float e0 = __expf(s0 - m), e1 = __expf(s1 - m);
            float ss = wredsum(e0 + e1);
            float inv = 1.f / ss;
            s.Alpha[lane]      = e0 * inv;
            s.Alpha[lane + 32] = e1 * inv;
        }
        __syncthreads();

        // att = alpha * V (into Kv1, stride 64, vectorized) ; A[d] -> g_A
        for (int i = tid * 4; i < NN * DD; i += NT * 4) {
            int e = i >> 6;
            float a = s.Alpha[e];
            float4 v = *(const float4*)&s.Kv[e * 128 + 64 + (i & 63)];
            *(float4*)&s.Kv1[i] = make_float4(a * v.x, a * v.y, a * v.z, a * v.w);
        }
        if (tid < DD) {
            float a = 0.f;
#pragma unroll 8
            for (int e = 0; e < NN; e++) a += s.Alpha[e] * s.Kv[e * 128 + 64 + tid];
            g_A[(nb + d) * DD + tid] = a;
        }
        __syncthreads();

        // GEMM2: t = silu(att @ phx_w1) ; phx[e] = t . phx_w2  — packed f32x2
        {
            const int r0 = wid * 4, j0 = lane * 2;
            u64 acc[4] = {};
#pragma unroll 4
            for (int k4 = 0; k4 < DD; k4 += 4) {
                float4 a0 = *(const float4*)&s.Kv1[(r0 + 0) * DD + k4];
                float4 a1 = *(const float4*)&s.Kv1[(r0 + 1) * DD + k4];
                float4 a2 = *(const float4*)&s.Kv1[(r0 + 2) * DD + k4];
                float4 a3 = *(const float4*)&s.Kv1[(r0 + 3) * DD + k4];
                const float* f0 = &a0.x; const float* f1 = &a1.x;
                const float* f2 = &a2.x; const float* f3 = &a3.x;
#pragma unroll
                for (int kk = 0; kk < 4; kk++) {
                    u64 bv = *(const u64*)&s.PhxW1[(k4 + kk) * DD + j0];
                    fma2(acc[0], dup2(f0[kk]), bv);
                    fma2(acc[1], dup2(f1[kk]), bv);
                    fma2(acc[2], dup2(f2[kk]), bv);
                    fma2(acc[3], dup2(f3[kk]), bv);
                }
            }
            float w0 = s.PhxW2[j0], w1 = s.PhxW2[j0 + 1];
#pragma unroll
            for (int i = 0; i < 4; i++) {
                float2 t = unpk(acc[i]);
                float p = wredsum(silu(t.x) * w0 + silu(t.y) * w1);
                if (lane == 0) s.Phx[r0 + i] = p;
            }
        }
        __syncthreads();

        // X_out[d] = Xn[d] + sum_e X_rel_norm[e] * phx[e]
        if (wid == 0) {
            float p0 = 0.f, p1 = 0.f, p2 = 0.f;
#pragma unroll
            for (int t2 = 0; t2 < 2; t2++) {
                int e = lane + 32 * t2;
                float w = s.Phx[e] / (1.f + sqrtf(s.Rd[e] + 1e-8f));
                p0 += s.Rel[e * 4 + 0] * w;
                p1 += s.Rel[e * 4 + 1] * w;
                p2 += s.Rel[e * 4 + 2] * w;
            }
            p0 = wredsum(p0); p1 = wredsum(p1); p2 = wredsum(p2);
            if (lane == 0) {
                Xout[(nb + d) * 3 + 0] = s.Xn[d * 4 + 0] + p0;
                Xout[(nb + d) * 3 + 1] = s.Xn[d * 4 + 1] + p1;
                Xout[(nb + d) * 3 + 2] = s.Xn[d * 4 + 2] + p2;
            }
        }
        __syncthreads();
    }

    // ---------------- phase 2: H_out ----------------
    for (int i = tid; i < DD * DD; i += NT) s.W2[i]        = phh_w1[i];
    for (int i = tid; i < DD * DD; i += NT) s.W2[4096 + i] = phh_w2[i];
    __syncthreads();

    // M = A^2 * H
    for (int i = tid; i < NN * DD; i += NT) {
        float a = g_A[nb * DD + i];
        s.Kv1[i] = a * a * s.H[i];
    }
    __syncthreads();

    // t = silu(M @ phh_w1 + b1) -> Kv (stride 64)
    {
        int r0 = wid * 4, j0 = lane * 2;
        float acc[4][2] = {};
#pragma unroll 8
        for (int k = 0; k < DD; k++) {
            float2 bv = *(const float2*)&s.W2[k * DD + j0];
#pragma unroll
            for (int i = 0; i < 4; i++) {
                float a = s.Kv1[(r0 + i) * DD + k];
                acc[i][0] += a * bv.x; acc[i][1] += a * bv.y;
            }
        }
#pragma unroll
        for (int i = 0; i < 4; i++) {
            s.Kv[(r0 + i) * DD + j0 + 0] = silu(acc[i][0] + s.B1[j0 + 0]);
            s.Kv[(r0 + i) * DD + j0 + 1] = silu(acc[i][1] + s.B1[j0 + 1]);
        }
    }
    __syncthreads();

    // H_out = H + t @ phh_w2 + b2
    {
        int r0 = wid * 4, j0 = lane * 2;
        float acc[4][2] = {};
#pragma unroll 8
        for (int k = 0; k < DD; k++) {
            float2 bv = *(const float2*)&s.W2[4096 + k * DD + j0];
#pragma unroll
            for (int i = 0; i < 4; i++) {
                float a = s.Kv[(r0 + i) * DD + k];
                acc[i][0] += a * bv.x; acc[i][1] += a * bv.y;
            }
        }
#pragma unroll
        for (int i = 0; i < 4; i++) {
            int n = r0 + i;
            Hout[(nb + n) * DD + j0 + 0] = s.H[n * DD + j0 + 0] + acc[i][0] + s.B2[j0 + 0];
            Hout[(nb + n) * DD + j0 + 1] = s.H[n * DD + j0 + 1] + acc[i][1] + s.B2[j0 + 1];
        }
    }
}

extern "C" void kernel_launch(void* const* d_in, const int* in_sizes, int n_in,
                              void* d_out, int out_size)
{
    const float* X      = (const float*)d_in[1];
    const float* Hg     = (const float*)d_in[2];
    const float* xnw    = (const float*)d_in[4];
    const float* q_w1   = (const float*)d_in[5];
    const float* q_w2   = (const float*)d_in[6];
    const float* kv_w1  = (const float*)d_in[7];
    const float* kv_w2  = (const float*)d_in[8];
    const float* qn_w   = (const float*)d_in[9];
    const float* qn_b   = (const float*)d_in[10];
    const float* kn_w   = (const float*)d_in[11];
    const float* kn_b   = (const float*)d_in[12];
    const float* phx_w1 = (const float*)d_in[13];
    const float* phx_w2 = (const float*)d_in[14];
    const float* phh_w1 = (const float*)d_in[15];
    const float* phh_b1 = (const float*)d_in[16];
    const float* phh_w2 = (const float*)d_in[17];
    const float* phh_b2 = (const float*)d_in[18];

    float* out  = (float*)d_out;
    float* Xout = out;
    float* Hout = out + BB * NN * 3;

    cudaFuncSetAttribute(se3_kernel, cudaFuncAttributeMaxDynamicSharedMemorySize,
                         (int)sizeof(Smem));

    se3_kernel<<<BB, NT, sizeof(Smem)>>>(X, Hg, xnw, q_w1, q_w2, kv_w1, kv_w2,
                                         qn_w, qn_b, kn_w, kn_b,
                                         phx_w1, phx_w2,
                                         phh_w1, phh_b1, phh_w2, phh_b2,
                                         Xout, Hout);
}

// round 6
// speedup vs baseline: 1.4026x; 1.2916x over previous
#include <cuda_runtime.h>
#include <math.h>

#define BB 128
#define NN 64
#define DD 64
#define NT 512

typedef unsigned long long u64;

// ---------------- shared memory layout (~218 KB) ----------------
struct Smem {
    float P[NN * 128];       // 32KB  H @ kv_w1[1:,:]
    float W2[128 * 128];     // 64KB  staging: q_w1/q_w2/kv_w1/kv_w2/phh
    float PhxW1[DD * DD];    // 16KB
    float Kv1[128 * 64];     // 32KB  A half-tile (kv1) / att tile / M scratch
    float Kv[128 * 128];     // 64KB  K|V pair output; H+Q0 in phase0; t in phase2
    float Qd[2 * DD];        // Q rows of the two active dsts
    float Xn[NN * 4];
    float Rel[128 * 4];
    float Rd[128];
    float Score[128];
    float Alpha[128];
    float Phx[128];
    float Apart[4 * 128];
    float W1r0[128];
    float PhxW2[DD];
    float QnW[DD], QnB[DD], KnW[DD], KnB[DD];
    float B1[DD], B2[DD];
    float meanNorm;
};

// static device scratch (no runtime alloc)
__device__ float g_A[BB * NN * DD];   // per-node attention aggregate
__device__ float g_Q[BB * NN * DD];   // LN'd per-node Q

__device__ __forceinline__ float wredsum(float v) {
#pragma unroll
    for (int o = 16; o > 0; o >>= 1) v += __shfl_xor_sync(0xffffffffu, v, o);
    return v;
}
__device__ __forceinline__ float wredmax(float v) {
#pragma unroll
    for (int o = 16; o > 0; o >>= 1) v = fmaxf(v, __shfl_xor_sync(0xffffffffu, v, o));
    return v;
}
// fast silu: MUFU.EX2 + MUFU.RCP path, rel err ~1e-7 (budget 1e-3)
__device__ __forceinline__ float silu(float x) {
    return __fdividef(x, 1.f + __expf(-x));
}

// ---- packed fp32x2 helpers ----
__device__ __forceinline__ void fma2(u64& d, u64 a, u64 b) {
    asm("fma.rn.f32x2 %0, %1, %2, %0;" : "+l"(d) : "l"(a), "l"(b));
}
__device__ __forceinline__ u64 dup2(float x) {
    u64 r; asm("mov.b64 %0, {%1, %1};" : "=l"(r) : "f"(x)); return r;
}
__device__ __forceinline__ float2 unpk(u64 v) {
    float2 r; asm("mov.b64 {%0, %1}, %2;" : "=f"(r.x), "=f"(r.y) : "l"(v)); return r;
}

__global__ __launch_bounds__(NT, 1)
void se3_kernel(const float* __restrict__ X, const float* __restrict__ Hg,
                const float* __restrict__ xnw,
                const float* __restrict__ q_w1, const float* __restrict__ q_w2,
                const float* __restrict__ kv_w1, const float* __restrict__ kv_w2,
                const float* __restrict__ qn_w, const float* __restrict__ qn_b,
                const float* __restrict__ kn_w, const float* __restrict__ kn_b,
                const float* __restrict__ phx_w1, const float* __restrict__ phx_w2,
                const float* __restrict__ phh_w1, const float* __restrict__ phh_b1,
                const float* __restrict__ phh_w2, const float* __restrict__ phh_b2,
                float* __restrict__ Xout, float* __restrict__ Hout)
{
    extern __shared__ char smem_raw[];
    Smem& s = *reinterpret_cast<Smem*>(smem_raw);

    const int tid  = threadIdx.x;
    const int lane = tid & 31;
    const int wid  = tid >> 5;
    const int nb   = blockIdx.x * NN;

    float* Hs = s.Kv;            // H lives here during phase 0 (64x64)
    float* Q0 = s.Kv + 4096;     // Q0 staging during phase 0

    // ---------------- phase 0: per-node precompute ----------------
    for (int i = tid; i < NN * DD; i += NT) Hs[i] = Hg[nb * DD + i];
    if (tid < DD) {
        s.QnW[tid] = qn_w[tid];  s.QnB[tid] = qn_b[tid];
        s.KnW[tid] = kn_w[tid];  s.KnB[tid] = kn_b[tid];
        s.PhxW2[tid] = phx_w2[tid];
        s.B1[tid] = phh_b1[tid]; s.B2[tid] = phh_b2[tid];
    }
    if (tid < NN) {
        float x0 = X[(nb + tid) * 3 + 0];
        float x1 = X[(nb + tid) * 3 + 1];
        float x2 = X[(nb + tid) * 3 + 2];
        s.Rd[tid] = sqrtf(x0 * x0 + x1 * x1 + x2 * x2);
        s.Xn[tid * 4 + 0] = x0; s.Xn[tid * 4 + 1] = x1; s.Xn[tid * 4 + 2] = x2;
    }
    for (int i = tid; i < DD * DD; i += NT) s.W2[i] = q_w1[i];
    __syncthreads();

    if (tid == 0) {
        float m = 0.f;
        for (int i = 0; i < NN; i++) m += s.Rd[i];
        s.meanNorm = m * (1.f / NN);
    }
    __syncthreads();

    if (tid < NN) {
        float sc = xnw[0] / (s.meanNorm + 1e-5f);
        s.Xn[tid * 4 + 0] *= sc; s.Xn[tid * 4 + 1] *= sc; s.Xn[tid * 4 + 2] *= sc;
    }

    // t1 = silu(H @ q_w1) -> Kv1 (stride 64)
    {
        int r0 = wid * 4, j0 = lane * 2;
        float acc[4][2] = {};
#pragma unroll 8
        for (int k = 0; k < DD; k++) {
            float2 bv = *(const float2*)&s.W2[k * DD + j0];
#pragma unroll
            for (int i = 0; i < 4; i++) {
                float a = Hs[(r0 + i) * DD + k];
                acc[i][0] += a * bv.x; acc[i][1] += a * bv.y;
            }
        }
#pragma unroll
        for (int i = 0; i < 4; i++) {
            s.Kv1[(r0 + i) * DD + j0 + 0] = silu(acc[i][0]);
            s.Kv1[(r0 + i) * DD + j0 + 1] = silu(acc[i][1]);
        }
    }
    __syncthreads();
    for (int i = tid; i < DD * DD; i += NT) s.W2[i] = q_w2[i];
    __syncthreads();

    // Q0 = t1 @ q_w2 (stride 64)
    {
        int r0 = wid * 4, j0 = lane * 2;
        float acc[4][2] = {};
#pragma unroll 8
        for (int k = 0; k < DD; k++) {
            float2 bv = *(const float2*)&s.W2[k * DD + j0];
#pragma unroll
            for (int i = 0; i < 4; i++) {
                float a = s.Kv1[(r0 + i) * DD + k];
                acc[i][0] += a * bv.x; acc[i][1] += a * bv.y;
            }
        }
#pragma unroll
        for (int i = 0; i < 4; i++) {
            Q0[(r0 + i) * DD + j0 + 0] = acc[i][0];
            Q0[(r0 + i) * DD + j0 + 1] = acc[i][1];
        }
    }
    __syncthreads();

    // LN(Q0) -> g_Q ; stage kv_w1 into W2
#pragma unroll
    for (int i = 0; i < 4; i++) {
        int r = wid * 4 + i;
        float v0 = Q0[r * DD + lane], v1 = Q0[r * DD + 32 + lane];
        float sum = wredsum(v0 + v1);
        float sq  = wredsum(v0 * v0 + v1 * v1);
        float mu  = sum * (1.f / DD);
        float var = sq * (1.f / DD) - mu * mu;
        float rstd = rsqrtf(var + 1e-5f);
        g_Q[(nb + r) * DD + lane]      = (v0 - mu) * rstd * s.QnW[lane]      + s.QnB[lane];
        g_Q[(nb + r) * DD + 32 + lane] = (v1 - mu) * rstd * s.QnW[lane + 32] + s.QnB[lane + 32];
    }
    for (int i = tid; i < 65 * 128; i += NT) s.W2[i] = kv_w1[i];
    __syncthreads();

    // P = H @ kv_w1[1:,:]  (64 x 128)
    {
        int r0 = wid * 4, c0 = lane * 4;
        float acc[4][4] = {};
#pragma unroll 8
        for (int k = 0; k < DD; k++) {
            float4 bv = *(const float4*)&s.W2[(1 + k) * 128 + c0];
#pragma unroll
            for (int i = 0; i < 4; i++) {
                float a = Hs[(r0 + i) * DD + k];
                acc[i][0] += a * bv.x; acc[i][1] += a * bv.y;
                acc[i][2] += a * bv.z; acc[i][3] += a * bv.w;
            }
        }
#pragma unroll
        for (int i = 0; i < 4; i++)
            *(float4*)&s.P[(r0 + i) * 128 + c0] =
                make_float4(acc[i][0], acc[i][1], acc[i][2], acc[i][3]);
    }
    if (tid < 128) s.W1r0[tid] = s.W2[tid];
    __syncthreads();

    for (int i = tid; i < 128 * 128; i += NT) s.W2[i] = kv_w2[i];
    for (int i = tid; i < DD * DD; i += NT) s.PhxW1[i] = phx_w1[i];
    __syncthreads();

    // ---------------- main loop: 32 iterations, 2 dst nodes each ----------------
    const int r0 = wid * 8;          // 16 warps x 8 edge-rows = 128 rows
    const int c0 = lane * 4;         // 128 output cols for GEMM1

    for (int p = 0; p < 32; p++) {
        const int d0 = 2 * p;

        // step 1: rel/rd for 128 edge-rows + fetch the two Q rows
        if (tid < 128) {
            int r = tid, sIdx = r & 63, dIdx = d0 + (r >> 6);
            float rx = s.Xn[sIdx * 4 + 0] - s.Xn[dIdx * 4 + 0];
            float ry = s.Xn[sIdx * 4 + 1] - s.Xn[dIdx * 4 + 1];
            float rz = s.Xn[sIdx * 4 + 2] - s.Xn[dIdx * 4 + 2];
            s.Rel[r * 4 + 0] = rx; s.Rel[r * 4 + 1] = ry; s.Rel[r * 4 + 2] = rz;
            s.Rd[r] = rx * rx + ry * ry + rz * rz;
            s.Qd[tid] = g_Q[(nb + dIdx) * DD + sIdx];   // Qd[dl*64 + c]
        }
        __syncthreads();

        // GEMM1: kv = silu(kv1) @ kv_w2   (128 x 128 x 128), K in 2 halves
        u64 acc[8][2] = {};
#pragma unroll
        for (int h = 0; h < 2; h++) {
            // build kv1 half: rows 0..127, local k 0..63
            for (int i = tid * 4; i < 128 * 64; i += NT * 4) {
                int r = i >> 6, kq = i & 63, src = r & 63;
                float rd = s.Rd[r];
                float4 pw = *(const float4*)&s.P[src * 128 + h * 64 + kq];
                float4 w  = *(const float4*)&s.W1r0[h * 64 + kq];
                float4 o;
                o.x = silu(fmaf(rd, w.x, pw.x));
                o.y = silu(fmaf(rd, w.y, pw.y));
                o.z = silu(fmaf(rd, w.z, pw.z));
                o.w = silu(fmaf(rd, w.w, pw.w));
                *(float4*)&s.Kv1[i] = o;
            }
            __syncthreads();

            const float* Wb = &s.W2[h * 64 * 128];
#pragma unroll 2
            for (int k4 = 0; k4 < 64; k4 += 4) {
                float4 a[8];
#pragma unroll
                for (int i = 0; i < 8; i++)
                    a[i] = *(const float4*)&s.Kv1[(r0 + i) * 64 + k4];
#pragma unroll
                for (int kk = 0; kk < 4; kk++) {
                    u64 b01 = *(const u64*)&Wb[(k4 + kk) * 128 + c0];
                    u64 b23 = *(const u64*)&Wb[(k4 + kk) * 128 + c0 + 2];
#pragma unroll
                    for (int i = 0; i < 8; i++) {
                        u64 dv = dup2(((const float*)&a[i])[kk]);
                        fma2(acc[i][0], dv, b01);
                        fma2(acc[i][1], dv, b23);
                    }
                }
            }
            if (h == 0) __syncthreads();   // before overwriting Kv1 with half 1
        }
        // write pair K|V tile
#pragma unroll
        for (int i = 0; i < 8; i++) {
            float2 lo = unpk(acc[i][0]);
            float2 hi = unpk(acc[i][1]);
            *(float4*)&s.Kv[(r0 + i) * 128 + c0] = make_float4(lo.x, lo.y, hi.x, hi.y);
        }
        __syncthreads();

        // LN(K) + score: warp handles 8 edge-rows
#pragma unroll
        for (int i = 0; i < 8; i++) {
            int r = r0 + i;
            float k0 = s.Kv[r * 128 + lane], k1 = s.Kv[r * 128 + 32 + lane];
            float sum = wredsum(k0 + k1);
            float sq  = wredsum(k0 * k0 + k1 * k1);
            float mu  = sum * (1.f / DD);
            float var = sq * (1.f / DD) - mu * mu;
            float rstd = rsqrtf(var + 1e-5f);
            float kh0 = (k0 - mu) * rstd * s.KnW[lane]      + s.KnB[lane];
            float kh1 = (k1 - mu) * rstd * s.KnW[lane + 32] + s.KnB[lane + 32];
            int qb = (r >> 6) * DD;
            float dot = wredsum(kh0 * s.Qd[qb + lane] + kh1 * s.Qd[qb + 32 + lane]);
            if (lane == 0) s.Score[r] = dot * 0.125f;
        }
        __syncthreads();

        // softmax: warp 0 -> d0, warp 1 -> d0+1  (mask self edge)
        if (wid < 2) {
            int base = wid * 64, dIdx = d0 + wid;
            float s0 = s.Score[base + lane], s1 = s.Score[base + 32 + lane];
            if (lane == dIdx)      s0 = -1e30f;
            if (lane + 32 == dIdx) s1 = -1e30f;
            float m  = wredmax(fmaxf(s0, s1));
            float e0 = __expf(s0 - m), e1 = __expf(s1 - m);
            float ss = wredsum(e0 + e1);
            float inv = __fdividef(1.f, ss);
            s.Alpha[base + lane]      = e0 * inv;
            s.Alpha[base + 32 + lane] = e1 * inv;
        }
        __syncthreads();

        // att = alpha * V -> Kv1 (stride 64) ; A partials in parallel
        for (int i = tid * 4; i < 128 * 64; i += NT * 4) {
            int r = i >> 6;
            float a = s.Alpha[r];
            float4 v = *(const float4*)&s.Kv[r * 128 + 64 + (i & 63)];
            *(float4*)&s.Kv1[i] = make_float4(a * v.x, a * v.y, a * v.z, a * v.w);
        }
        {
            int g = tid >> 7, q = tid & 127, dl = q >> 6, c = q & 63;
            float acc4 = 0.f;
#pragma unroll
            for (int e = 0; e < 16; e++) {
                int rr = dl * 64 + g * 16 + e;
                acc4 += s.Alpha[rr] * s.Kv[rr * 128 + 64 + c];
            }
            s.Apart[tid] = acc4;
        }
        __syncthreads();
        if (tid < 128) {
            float a = s.Apart[tid] + s.Apart[128 + tid] + s.Apart[256 + tid] + s.Apart[384 + tid];
            g_A[(nb + d0 + (tid >> 6)) * DD + (tid & 63)] = a;
        }

        // GEMM2: t = silu(att @ phx_w1) ; phx = t . phx_w2
        {
            const int j0 = lane * 2;
            u64 acc2[8] = {};
#pragma unroll 2
            for (int k4 = 0; k4 < DD; k4 += 4) {
                float4 a[8];
#pragma unroll
                for (int i = 0; i < 8; i++)
                    a[i] = *(const float4*)&s.Kv1[(r0 + i) * 64 + k4];
#pragma unroll
                for (int kk = 0; kk < 4; kk++) {
                    u64 bv = *(const u64*)&s.PhxW1[(k4 + kk) * DD + j0];
#pragma unroll
                    for (int i = 0; i < 8; i++)
                        fma2(acc2[i], dup2(((const float*)&a[i])[kk]), bv);
                }
            }
            float w0 = s.PhxW2[j0], w1 = s.PhxW2[j0 + 1];
#pragma unroll
            for (int i = 0; i < 8; i++) {
                float2 t = unpk(acc2[i]);
                float pv = wredsum(silu(t.x) * w0 + silu(t.y) * w1);
                if (lane == 0) s.Phx[r0 + i] = pv;
            }
        }
        __syncthreads();

        // X_out for both dsts: warp 0 -> d0, warp 1 -> d0+1
        if (wid < 2) {
            int base = wid * 64, dIdx = d0 + wid;
            float p0 = 0.f, p1 = 0.f, p2 = 0.f;
#pragma unroll
            for (int t2 = 0; t2 < 2; t2++) {
                int r = base + lane + 32 * t2;
                float wgt = __fdividef(s.Phx[r], 1.f + sqrtf(s.Rd[r] + 1e-8f));
                p0 += s.Rel[r * 4 + 0] * wgt;
                p1 += s.Rel[r * 4 + 1] * wgt;
                p2 += s.Rel[r * 4 + 2] * wgt;
            }
            p0 = wredsum(p0); p1 = wredsum(p1); p2 = wredsum(p2);
            if (lane == 0) {
                Xout[(nb + dIdx) * 3 + 0] = s.Xn[dIdx * 4 + 0] + p0;
                Xout[(nb + dIdx) * 3 + 1] = s.Xn[dIdx * 4 + 1] + p1;
                Xout[(nb + dIdx) * 3 + 2] = s.Xn[dIdx * 4 + 2] + p2;
            }
        }
        __syncthreads();   // end-of-pair: protects Rel/Rd/Qd/Phx reuse
    }

    // ---------------- phase 2: H_out ----------------
    for (int i = tid; i < DD * DD; i += NT) s.W2[i]        = phh_w1[i];
    for (int i = tid; i < DD * DD; i += NT) s.W2[4096 + i] = phh_w2[i];
    __syncthreads();

    // M = A^2 * H
    for (int i = tid; i < NN * DD; i += NT) {
        float a = g_A[nb * DD + i];
        s.Kv1[i] = a * a * Hg[nb * DD + i];
    }
    __syncthreads();

    // t = silu(M @ phh_w1 + b1) -> s.Kv (stride 64)
    {
        int rr0 = wid * 4, j0 = lane * 2;
        float acc[4][2] = {};
#pragma unroll 8
        for (int k = 0; k < DD; k++) {
            float2 bv = *(const float2*)&s.W2[k * DD + j0];
#pragma unroll
            for (int i = 0; i < 4; i++) {
                float a = s.Kv1[(rr0 + i) * DD + k];
                acc[i][0] += a * bv.x; acc[i][1] += a * bv.y;
            }
        }
#pragma unroll
        for (int i = 0; i < 4; i++) {
            s.Kv[(rr0 + i) * DD + j0 + 0] = silu(acc[i][0] + s.B1[j0 + 0]);
            s.Kv[(rr0 + i) * DD + j0 + 1] = silu(acc[i][1] + s.B1[j0 + 1]);
        }
    }
    __syncthreads();

    // H_out = H + t @ phh_w2 + b2
    {
        int rr0 = wid * 4, j0 = lane * 2;
        float acc[4][2] = {};
#pragma unroll 8
        for (int k = 0; k < DD; k++) {
            float2 bv = *(const float2*)&s.W2[4096 + k * DD + j0];
#pragma unroll
            for (int i = 0; i < 4; i++) {
                float a = s.Kv[(rr0 + i) * DD + k];
                acc[i][0] += a * bv.x; acc[i][1] += a * bv.y;
            }
        }
#pragma unroll
        for (int i = 0; i < 4; i++) {
            int n = rr0 + i;
            Hout[(nb + n) * DD + j0 + 0] = Hg[(nb + n) * DD + j0 + 0] + acc[i][0] + s.B2[j0 + 0];
            Hout[(nb + n) * DD + j0 + 1] = Hg[(nb + n) * DD + j0 + 1] + acc[i][1] + s.B2[j0 + 1];
        }
    }
}

extern "C" void kernel_launch(void* const* d_in, const int* in_sizes, int n_in,
                              void* d_out, int out_size)
{
    const float* X      = (const float*)d_in[1];
    const float* Hg     = (const float*)d_in[2];
    const float* xnw    = (const float*)d_in[4];
    const float* q_w1   = (const float*)d_in[5];
    const float* q_w2   = (const float*)d_in[6];
    const float* kv_w1  = (const float*)d_in[7];
    const float* kv_w2  = (const float*)d_in[8];
    const float* qn_w   = (const float*)d_in[9];
    const float* qn_b   = (const float*)d_in[10];
    const float* kn_w   = (const float*)d_in[11];
    const float* kn_b   = (const float*)d_in[12];
    const float* phx_w1 = (const float*)d_in[13];
    const float* phx_w2 = (const float*)d_in[14];
    const float* phh_w1 = (const float*)d_in[15];
    const float* phh_b1 = (const float*)d_in[16];
    const float* phh_w2 = (const float*)d_in[17];
    const float* phh_b2 = (const float*)d_in[18];

    float* out  = (float*)d_out;
    float* Xout = out;
    float* Hout = out + BB * NN * 3;

    cudaFuncSetAttribute(se3_kernel, cudaFuncAttributeMaxDynamicSharedMemorySize,
                         (int)sizeof(Smem));

    se3_kernel<<<BB, NT, sizeof(Smem)>>>(X, Hg, xnw, q_w1, q_w2, kv_w1, kv_w2,
                                         qn_w, qn_b, kn_w, kn_b,
                                         phx_w1, phx_w2,
                                         phh_w1, phh_b1, phh_w2, phh_b2,
                                         Xout, Hout);
}

// round 8
// speedup vs baseline: 1.9326x; 1.3779x over previous
#include <cuda_runtime.h>
#include <cuda_bf16.h>
#include <math.h>
#include <stdint.h>

#define BB 128
#define NN 64
#define DD 64
#define NT 512

typedef unsigned long long u64;

// ---------------- shared memory layout (~190 KB) ----------------
struct SmallS {
    float Qd[128];
    float Xn[NN * 4];
    float Rel[128 * 4];
    float Rd[128];
    float Score[128];
    float Alpha[128];
    float Phx[128];
    float Apart[512];
    float W1r0[128];
    float PhxW2[DD];
    float QnW[DD], QnB[DD], KnW[DD], KnB[DD];
    float B1[DD], B2[DD];
    float meanNorm;
};

struct Smem {
    __nv_bfloat16 Ahi[128 * 128];   // 32KB @ 0      iter: A-split hi | C fp32 tile spans Ahi+Alo | phase0: AREG staging
    __nv_bfloat16 Alo[128 * 128];   // 32KB @ 32768  iter: A-split lo
    __nv_bfloat16 Bhi[128 * 128];   // 32KB @ 65536  kv_w2^T hi | phase0: Hs/T1 fp32 | phase2: M/t
    __nv_bfloat16 Blo[128 * 128];   // 32KB @ 98304  kv_w2^T lo | phase0: Q0 fp32
    float P[NN * 128];              // 32KB
    float PhxW1[DD * DD];           // 16KB
    SmallS sm;
};

#define OFF_AHI 0u
#define OFF_ALO 32768u
#define OFF_BHI 65536u
#define OFF_BLO 98304u

// static device scratch
__device__ float g_A[BB * NN * DD];
__device__ float g_Q[BB * NN * DD];

__device__ __forceinline__ float wredsum(float v) {
#pragma unroll
    for (int o = 16; o > 0; o >>= 1) v += __shfl_xor_sync(0xffffffffu, v, o);
    return v;
}
__device__ __forceinline__ float wredmax(float v) {
#pragma unroll
    for (int o = 16; o > 0; o >>= 1) v = fmaxf(v, __shfl_xor_sync(0xffffffffu, v, o));
    return v;
}
// silu via single-MUFU tanh: silu(x) = 0.5x + 0.5x*tanh(x/2)
__device__ __forceinline__ float silu(float x) {
    float t, hx = 0.5f * x;
    asm("tanh.approx.f32 %0, %1;" : "=f"(t) : "f"(hx));
    return fmaf(hx, t, hx);
}

// packed fp32x2 (GEMM2)
__device__ __forceinline__ void fma2(u64& d, u64 a, u64 b) {
    asm("fma.rn.f32x2 %0, %1, %2, %0;" : "+l"(d) : "l"(a), "l"(b));
}
__device__ __forceinline__ u64 dup2(float x) {
    u64 r; asm("mov.b64 %0, {%1, %1};" : "=l"(r) : "f"(x)); return r;
}
__device__ __forceinline__ float2 unpk(u64 v) {
    float2 r; asm("mov.b64 {%0, %1}, %2;" : "=f"(r.x), "=f"(r.y) : "l"(v)); return r;
}

__device__ __forceinline__ uint32_t smem_u32(const void* p) {
    return (uint32_t)__cvta_generic_to_shared(p);
}
__device__ __forceinline__ uint32_t pack_bf2(float a, float b) {
    __nv_bfloat162 h; h.x = __float2bfloat16(a); h.y = __float2bfloat16(b);
    return *(uint32_t*)&h;
}

// ---- mma.sync / ldmatrix (standard PTX, works on compute_103) ----
__device__ __forceinline__ void ldm4(uint32_t* r, uint32_t addr) {
    asm volatile("ldmatrix.sync.aligned.m8n8.x4.shared.b16 {%0,%1,%2,%3}, [%4];"
                 : "=r"(r[0]), "=r"(r[1]), "=r"(r[2]), "=r"(r[3]) : "r"(addr));
}
__device__ __forceinline__ void mma16816(float* d, const uint32_t* a, const uint32_t* b) {
    asm volatile(
        "mma.sync.aligned.m16n8k16.row.col.f32.bf16.bf16.f32 "
        "{%0,%1,%2,%3}, {%4,%5,%6,%7}, {%8,%9}, {%0,%1,%2,%3};"
        : "+f"(d[0]), "+f"(d[1]), "+f"(d[2]), "+f"(d[3])
        : "r"(a[0]), "r"(a[1]), "r"(a[2]), "r"(a[3]), "r"(b[0]), "r"(b[1]));
}

// bf16 tile: row-major 128x128, 256B rows, 16B-chunk XOR swizzle (conflict-free ldmatrix)
__device__ __forceinline__ uint32_t ABaddr(uint32_t base, int r, int ck) {
    return base + ((uint32_t)r << 8) + ((uint32_t)(ck ^ (r & 7)) << 4);
}
// C fp32 tile index: row-major 128x128, same 16B-chunk XOR swizzle
__device__ __forceinline__ int CI(int r, int c) {
    return (r << 7) + ((((c >> 2) ^ (r & 7)) << 2) | (c & 3));
}

__global__ __launch_bounds__(NT, 1)
void se3_kernel(const float* __restrict__ X, const float* __restrict__ Hg,
                const float* __restrict__ xnw,
                const float* __restrict__ q_w1, const float* __restrict__ q_w2,
                const float* __restrict__ kv_w1, const float* __restrict__ kv_w2,
                const float* __restrict__ qn_w, const float* __restrict__ qn_b,
                const float* __restrict__ kn_w, const float* __restrict__ kn_b,
                const float* __restrict__ phx_w1, const float* __restrict__ phx_w2,
                const float* __restrict__ phh_w1, const float* __restrict__ phh_b1,
                const float* __restrict__ phh_w2, const float* __restrict__ phh_b2,
                float* __restrict__ Xout, float* __restrict__ Hout)
{
    extern __shared__ char smem_raw[];
    Smem& s = *reinterpret_cast<Smem*>(smem_raw);

    const int tid  = threadIdx.x;
    const int lane = tid & 31;
    const int wid  = tid >> 5;
    const int nb   = blockIdx.x * NN;
    const uint32_t sb = smem_u32(smem_raw);

    float* AREG = (float*)s.Ahi;          // 16384 fp32 (Ahi+Alo span) staging
    float* Cf   = (float*)s.Ahi;          // C fp32 tile (after MMA)
    float* Hs   = (float*)s.Bhi;          // 64x64 (phase 0)
    float* T1   = (float*)s.Bhi + 4096;   // 64x64 (phase 0)
    float* Q0   = (float*)s.Blo;          // 64x64 (phase 0)

    // ---------------- phase 0 ----------------
    for (int i = tid; i < NN * DD; i += NT) Hs[i] = Hg[nb * DD + i];
    if (tid < DD) {
        s.sm.QnW[tid] = qn_w[tid];  s.sm.QnB[tid] = qn_b[tid];
        s.sm.KnW[tid] = kn_w[tid];  s.sm.KnB[tid] = kn_b[tid];
        s.sm.PhxW2[tid] = phx_w2[tid];
        s.sm.B1[tid] = phh_b1[tid]; s.sm.B2[tid] = phh_b2[tid];
    }
    if (tid < NN) {
        float x0 = X[(nb + tid) * 3 + 0];
        float x1 = X[(nb + tid) * 3 + 1];
        float x2 = X[(nb + tid) * 3 + 2];
        s.sm.Rd[tid] = sqrtf(x0 * x0 + x1 * x1 + x2 * x2);
        s.sm.Xn[tid * 4 + 0] = x0; s.sm.Xn[tid * 4 + 1] = x1; s.sm.Xn[tid * 4 + 2] = x2;
    }
    for (int i = tid; i < DD * DD; i += NT) AREG[i] = q_w1[i];
    __syncthreads();

    if (tid == 0) {
        float m = 0.f;
        for (int i = 0; i < NN; i++) m += s.sm.Rd[i];
        s.sm.meanNorm = m * (1.f / NN);
    }
    __syncthreads();

    if (tid < NN) {
        float sc = xnw[0] / (s.sm.meanNorm + 1e-5f);
        s.sm.Xn[tid * 4 + 0] *= sc; s.sm.Xn[tid * 4 + 1] *= sc; s.sm.Xn[tid * 4 + 2] *= sc;
    }

    // t1 = silu(H @ q_w1)
    {
        int r0 = wid * 4, j0 = lane * 2;
        float acc[4][2] = {};
#pragma unroll 8
        for (int k = 0; k < DD; k++) {
            float2 bv = *(const float2*)&AREG[k * DD + j0];
#pragma unroll
            for (int i = 0; i < 4; i++) {
                float a = Hs[(r0 + i) * DD + k];
                acc[i][0] += a * bv.x; acc[i][1] += a * bv.y;
            }
        }
#pragma unroll
        for (int i = 0; i < 4; i++) {
            T1[(r0 + i) * DD + j0 + 0] = silu(acc[i][0]);
            T1[(r0 + i) * DD + j0 + 1] = silu(acc[i][1]);
        }
    }
    __syncthreads();
    for (int i = tid; i < DD * DD; i += NT) AREG[i] = q_w2[i];
    __syncthreads();

    // Q0 = t1 @ q_w2
    {
        int r0 = wid * 4, j0 = lane * 2;
        float acc[4][2] = {};
#pragma unroll 8
        for (int k = 0; k < DD; k++) {
            float2 bv = *(const float2*)&AREG[k * DD + j0];
#pragma unroll
            for (int i = 0; i < 4; i++) {
                float a = T1[(r0 + i) * DD + k];
                acc[i][0] += a * bv.x; acc[i][1] += a * bv.y;
            }
        }
#pragma unroll
        for (int i = 0; i < 4; i++) {
            Q0[(r0 + i) * DD + j0 + 0] = acc[i][0];
            Q0[(r0 + i) * DD + j0 + 1] = acc[i][1];
        }
    }
    __syncthreads();

    // LN(Q0) -> g_Q ; stage kv_w1
#pragma unroll
    for (int i = 0; i < 4; i++) {
        int r = wid * 4 + i;
        float v0 = Q0[r * DD + lane], v1 = Q0[r * DD + 32 + lane];
        float sum = wredsum(v0 + v1);
        float sq  = wredsum(v0 * v0 + v1 * v1);
        float mu  = sum * (1.f / DD);
        float var = sq * (1.f / DD) - mu * mu;
        float rstd = rsqrtf(var + 1e-5f);
        g_Q[(nb + r) * DD + lane]      = (v0 - mu) * rstd * s.sm.QnW[lane]      + s.sm.QnB[lane];
        g_Q[(nb + r) * DD + 32 + lane] = (v1 - mu) * rstd * s.sm.QnW[lane + 32] + s.sm.QnB[lane + 32];
    }
    __syncthreads();
    for (int i = tid; i < 65 * 128; i += NT) AREG[i] = kv_w1[i];
    __syncthreads();

    // P = H @ kv_w1[1:,:]
    {
        int r0 = wid * 4, c0 = lane * 4;
        float acc[4][4] = {};
#pragma unroll 8
        for (int k = 0; k < DD; k++) {
            float4 bv = *(const float4*)&AREG[(1 + k) * 128 + c0];
#pragma unroll
            for (int i = 0; i < 4; i++) {
                float a = Hs[(r0 + i) * DD + k];
                acc[i][0] += a * bv.x; acc[i][1] += a * bv.y;
                acc[i][2] += a * bv.z; acc[i][3] += a * bv.w;
            }
        }
#pragma unroll
        for (int i = 0; i < 4; i++)
            *(float4*)&s.P[(r0 + i) * 128 + c0] =
                make_float4(acc[i][0], acc[i][1], acc[i][2], acc[i][3]);
    }
    if (tid < 128) s.sm.W1r0[tid] = AREG[tid];
    __syncthreads();

    // stage kv_w2 fp32, then transpose + bf16-split into Bhi/Blo (n-major rows, k contiguous)
    for (int i = tid; i < 128 * 128; i += NT) AREG[i] = kv_w2[i];
    for (int i = tid; i < DD * DD; i += NT) s.PhxW1[i] = phx_w1[i];
    __syncthreads();
    for (int slot = tid; slot < 2048; slot += NT) {
        int ck = slot >> 7, n = slot & 127;     // chunk = 8 k-values
        uint32_t hi[4], lo[4];
#pragma unroll
        for (int j = 0; j < 4; j++) {
            float x0 = AREG[(ck * 8 + 2 * j) * 128 + n];
            float x1 = AREG[(ck * 8 + 2 * j + 1) * 128 + n];
            __nv_bfloat16 h0 = __float2bfloat16(x0), h1 = __float2bfloat16(x1);
            __nv_bfloat162 hp; hp.x = h0; hp.y = h1;
            hi[j] = *(uint32_t*)&hp;
            lo[j] = pack_bf2(x0 - __bfloat162float(h0), x1 - __bfloat162float(h1));
        }
        *(uint4*)(smem_raw + ABaddr(OFF_BHI, n, ck)) = make_uint4(hi[0], hi[1], hi[2], hi[3]);
        *(uint4*)(smem_raw + ABaddr(OFF_BLO, n, ck)) = make_uint4(lo[0], lo[1], lo[2], lo[3]);
    }
    __syncthreads();

    // ---------------- main loop: 32 iterations, 2 dst nodes each ----------------
    const int r0 = wid * 8;

    for (int p = 0; p < 32; p++) {
        const int d0 = 2 * p;

        // 1) rel/rd + Q rows
        if (tid < 128) {
            int r = tid, sIdx = r & 63, dIdx = d0 + (r >> 6);
            float rx = s.sm.Xn[sIdx * 4 + 0] - s.sm.Xn[dIdx * 4 + 0];
            float ry = s.sm.Xn[sIdx * 4 + 1] - s.sm.Xn[dIdx * 4 + 1];
            float rz = s.sm.Xn[sIdx * 4 + 2] - s.sm.Xn[dIdx * 4 + 2];
            s.sm.Rel[r * 4 + 0] = rx; s.sm.Rel[r * 4 + 1] = ry; s.sm.Rel[r * 4 + 2] = rz;
            s.sm.Rd[r] = rx * rx + ry * ry + rz * rz;
            s.sm.Qd[tid] = g_Q[(nb + dIdx) * DD + sIdx];
        }
        __syncthreads();

        // 2) build A = silu(rd*w1row0 + P) as bf16 hi/lo (swizzled row-major)
        for (int slot = tid; slot < 2048; slot += NT) {
            int r = slot >> 4, ck = slot & 15, src = r & 63;
            float rd = s.sm.Rd[r];
            float4 pa = *(const float4*)&s.P[src * 128 + ck * 8];
            float4 pb = *(const float4*)&s.P[src * 128 + ck * 8 + 4];
            float4 wa = *(const float4*)&s.sm.W1r0[ck * 8];
            float4 wb = *(const float4*)&s.sm.W1r0[ck * 8 + 4];
            float v[8];
            v[0] = silu(fmaf(rd, wa.x, pa.x)); v[1] = silu(fmaf(rd, wa.y, pa.y));
            v[2] = silu(fmaf(rd, wa.z, pa.z)); v[3] = silu(fmaf(rd, wa.w, pa.w));
            v[4] = silu(fmaf(rd, wb.x, pb.x)); v[5] = silu(fmaf(rd, wb.y, pb.y));
            v[6] = silu(fmaf(rd, wb.z, pb.z)); v[7] = silu(fmaf(rd, wb.w, pb.w));
            uint32_t hi[4], lo[4];
#pragma unroll
            for (int j = 0; j < 4; j++) {
                float x0 = v[2 * j], x1 = v[2 * j + 1];
                __nv_bfloat16 h0 = __float2bfloat16(x0), h1 = __float2bfloat16(x1);
                __nv_bfloat162 hp; hp.x = h0; hp.y = h1;
                hi[j] = *(uint32_t*)&hp;
                lo[j] = pack_bf2(x0 - __bfloat162float(h0), x1 - __bfloat162float(h1));
            }
            *(uint4*)(smem_raw + ABaddr(OFF_AHI, r, ck)) = make_uint4(hi[0], hi[1], hi[2], hi[3]);
            *(uint4*)(smem_raw + ABaddr(OFF_ALO, r, ck)) = make_uint4(lo[0], lo[1], lo[2], lo[3]);
        }
        __syncthreads();

        // 3) GEMM1 via mma.sync: C = Ahi*Bhi + Alo*Bhi + Ahi*Blo  (128x128x128)
        {
            const int wm = wid >> 2, wn = wid & 3;
            const int la15 = lane & 15, lhi = lane >> 4, la7 = lane & 7, lb8 = (lane >> 3) & 1;
            const int rA0 = 32 * wm + la15, rA1 = rA0 + 16;
            const int rB0 = 32 * wn + (lhi << 3) + la7, rB1 = rB0 + 16;
            float acc[32];
#pragma unroll
            for (int i = 0; i < 32; i++) acc[i] = 0.f;

#pragma unroll
            for (int ks = 0; ks < 8; ks++) {
                const int ckA = 2 * ks + lhi, ckB = 2 * ks + lb8;
                uint32_t ah0[4], ah1[4], bb0[4], bb1[4], t0[4], t1[4];
                ldm4(ah0, ABaddr(sb + OFF_AHI, rA0, ckA));
                ldm4(ah1, ABaddr(sb + OFF_AHI, rA1, ckA));
                ldm4(bb0, ABaddr(sb + OFF_BHI, rB0, ckB));
                ldm4(bb1, ABaddr(sb + OFF_BHI, rB1, ckB));
#pragma unroll
                for (int j = 0; j < 4; j++) {
                    const uint32_t* bv = (j < 2 ? bb0 : bb1) + (j & 1) * 2;
                    mma16816(&acc[j * 4],      ah0, bv);
                    mma16816(&acc[16 + j * 4], ah1, bv);
                }
                ldm4(t0, ABaddr(sb + OFF_ALO, rA0, ckA));
                ldm4(t1, ABaddr(sb + OFF_ALO, rA1, ckA));
#pragma unroll
                for (int j = 0; j < 4; j++) {
                    const uint32_t* bv = (j < 2 ? bb0 : bb1) + (j & 1) * 2;
                    mma16816(&acc[j * 4],      t0, bv);
                    mma16816(&acc[16 + j * 4], t1, bv);
                }
                ldm4(bb0, ABaddr(sb + OFF_BLO, rB0, ckB));
                ldm4(bb1, ABaddr(sb + OFF_BLO, rB1, ckB));
#pragma unroll
                for (int j = 0; j < 4; j++) {
                    const uint32_t* bv = (j < 2 ? bb0 : bb1) + (j & 1) * 2;
                    mma16816(&acc[j * 4],      ah0, bv);
                    mma16816(&acc[16 + j * 4], ah1, bv);
                }
            }
            __syncthreads();   // all ldmatrix reads of A done before C overwrites it

            // 4) store C (fp32, swizzled) over the A region
            const int rq = lane >> 2, cq = (lane & 3) << 1;
#pragma unroll
            for (int i = 0; i < 2; i++)
#pragma unroll
                for (int j = 0; j < 4; j++) {
                    int r = 32 * wm + 16 * i + rq;
                    int c = 32 * wn + 8 * j + cq;
                    float* d = &acc[(i * 4 + j) * 4];
                    *(float2*)&Cf[CI(r, c)]     = make_float2(d[0], d[1]);
                    *(float2*)&Cf[CI(r + 8, c)] = make_float2(d[2], d[3]);
                }
        }
        __syncthreads();

        // 5) LN(K) + score (K = C[:,0:64])
#pragma unroll
        for (int i = 0; i < 8; i++) {
            int r = r0 + i;
            float k0 = Cf[CI(r, lane)], k1 = Cf[CI(r, lane + 32)];
            float sum = wredsum(k0 + k1);
            float sq  = wredsum(k0 * k0 + k1 * k1);
            float mu  = sum * (1.f / DD);
            float var = sq * (1.f / DD) - mu * mu;
            float rstd = rsqrtf(var + 1e-5f);
            float kh0 = (k0 - mu) * rstd * s.sm.KnW[lane]      + s.sm.KnB[lane];
            float kh1 = (k1 - mu) * rstd * s.sm.KnW[lane + 32] + s.sm.KnB[lane + 32];
            int qb = (r >> 6) * DD;
            float dot = wredsum(kh0 * s.sm.Qd[qb + lane] + kh1 * s.sm.Qd[qb + 32 + lane]);
            if (lane == 0) s.sm.Score[r] = dot * 0.125f;
        }
        __syncthreads();

        // 6) softmax (mask self)
        if (wid < 2) {
            int base = wid * 64, dIdx = d0 + wid;
            float s0 = s.sm.Score[base + lane], s1 = s.sm.Score[base + 32 + lane];
            if (lane == dIdx)      s0 = -1e30f;
            if (lane + 32 == dIdx) s1 = -1e30f;
            float m  = wredmax(fmaxf(s0, s1));
            float e0 = __expf(s0 - m), e1 = __expf(s1 - m);
            float ss = wredsum(e0 + e1);
            float inv = __fdividef(1.f, ss);
            s.sm.Alpha[base + lane]      = e0 * inv;
            s.sm.Alpha[base + 32 + lane] = e1 * inv;
        }
        __syncthreads();

        // 7) A-aggregate partials (V = C[:,64:128]) + GEMM2 (att = alpha*V on the fly)
        {
            int g = tid >> 7, q = tid & 127, dl = q >> 6, c = q & 63;
            float acc4 = 0.f;
#pragma unroll
            for (int e = 0; e < 16; e++) {
                int rr = dl * 64 + g * 16 + e;
                acc4 += s.sm.Alpha[rr] * Cf[CI(rr, 64 + c)];
            }
            s.sm.Apart[tid] = acc4;
        }
        {
            const int j0 = lane * 2;
            float alf[8];
#pragma unroll
            for (int i = 0; i < 8; i++) alf[i] = s.sm.Alpha[r0 + i];
            u64 acc2[8] = {};
#pragma unroll 2
            for (int k4 = 0; k4 < DD; k4 += 4) {
                float4 a[8];
#pragma unroll
                for (int i = 0; i < 8; i++)
                    a[i] = *(const float4*)&Cf[CI(r0 + i, 64 + k4)];
#pragma unroll
                for (int kk = 0; kk < 4; kk++) {
                    u64 bv = *(const u64*)&s.PhxW1[(k4 + kk) * DD + j0];
#pragma unroll
                    for (int i = 0; i < 8; i++)
                        fma2(acc2[i], dup2(alf[i] * ((const float*)&a[i])[kk]), bv);
                }
            }
            float w0 = s.sm.PhxW2[j0], w1 = s.sm.PhxW2[j0 + 1];
#pragma unroll
            for (int i = 0; i < 8; i++) {
                float2 t = unpk(acc2[i]);
                float pv = wredsum(silu(t.x) * w0 + silu(t.y) * w1);
                if (lane == 0) s.sm.Phx[r0 + i] = pv;
            }
        }
        __syncthreads();

        // 8) g_A write + X_out
        if (tid < 128) {
            float a = s.sm.Apart[tid] + s.sm.Apart[128 + tid]
                    + s.sm.Apart[256 + tid] + s.sm.Apart[384 + tid];
            g_A[(nb + d0 + (tid >> 6)) * DD + (tid & 63)] = a;
        }
        if (wid < 2) {
            int base = wid * 64, dIdx = d0 + wid;
            float p0 = 0.f, p1 = 0.f, p2 = 0.f;
#pragma unroll
            for (int t2 = 0; t2 < 2; t2++) {
                int r = base + lane + 32 * t2;
                float wgt = __fdividef(s.sm.Phx[r], 1.f + sqrtf(s.sm.Rd[r] + 1e-8f));
                p0 += s.sm.Rel[r * 4 + 0] * wgt;
                p1 += s.sm.Rel[r * 4 + 1] * wgt;
                p2 += s.sm.Rel[r * 4 + 2] * wgt;
            }
            p0 = wredsum(p0); p1 = wredsum(p1); p2 = wredsum(p2);
            if (lane == 0) {
                Xout[(nb + dIdx) * 3 + 0] = s.sm.Xn[dIdx * 4 + 0] + p0;
                Xout[(nb + dIdx) * 3 + 1] = s.sm.Xn[dIdx * 4 + 1] + p1;
                Xout[(nb + dIdx) * 3 + 2] = s.sm.Xn[dIdx * 4 + 2] + p2;
            }
        }
        __syncthreads();
    }

    // ---------------- phase 2: H_out ----------------
    float* Mb = (float*)s.Bhi;          // 64x64
    float* Tb = (float*)s.Bhi + 4096;   // 64x64
    for (int i = tid; i < DD * DD; i += NT) AREG[i]        = phh_w1[i];
    for (int i = tid; i < DD * DD; i += NT) AREG[4096 + i] = phh_w2[i];
    __syncthreads();

    // M = A^2 * H
    for (int i = tid; i < NN * DD; i += NT) {
        float a = g_A[nb * DD + i];
        Mb[i] = a * a * Hg[nb * DD + i];
    }
    __syncthreads();

    // t = silu(M @ phh_w1 + b1)
    {
        int rr0 = wid * 4, j0 = lane * 2;
        float acc[4][2] = {};
#pragma unroll 8
        for (int k = 0; k < DD; k++) {
            float2 bv = *(const float2*)&AREG[k * DD + j0];
#pragma unroll
            for (int i = 0; i < 4; i++) {
                float a = Mb[(rr0 + i) * DD + k];
                acc[i][0] += a * bv.x; acc[i][1] += a * bv.y;
            }
        }
#pragma unroll
        for (int i = 0; i < 4; i++) {
            Tb[(rr0 + i) * DD + j0 + 0] = silu(acc[i][0] + s.sm.B1[j0 + 0]);
            Tb[(rr0 + i) * DD + j0 + 1] = silu(acc[i][1] + s.sm.B1[j0 + 1]);
        }
    }
    __syncthreads();

    // H_out = H + t @ phh_w2 + b2
    {
        int rr0 = wid * 4, j0 = lane * 2;
        float acc[4][2] = {};
#pragma unroll 8
        for (int k = 0; k < DD; k++) {
            float2 bv = *(const float2*)&AREG[4096 + k * DD + j0];
#pragma unroll
            for (int i = 0; i < 4; i++) {
                float a = Tb[(rr0 + i) * DD + k];
                acc[i][0] += a * bv.x; acc[i][1] += a * bv.y;
            }
        }
#pragma unroll
        for (int i = 0; i < 4; i++) {
            int n = rr0 + i;
            Hout[(nb + n) * DD + j0 + 0] = Hg[(nb + n) * DD + j0 + 0] + acc[i][0] + s.sm.B2[j0 + 0];
            Hout[(nb + n) * DD + j0 + 1] = Hg[(nb + n) * DD + j0 + 1] + acc[i][1] + s.sm.B2[j0 + 1];
        }
    }
}

extern "C" void kernel_launch(void* const* d_in, const int* in_sizes, int n_in,
                              void* d_out, int out_size)
{
    const float* X      = (const float*)d_in[1];
    const float* Hg     = (const float*)d_in[2];
    const float* xnw    = (const float*)d_in[4];
    const float* q_w1   = (const float*)d_in[5];
    const float* q_w2   = (const float*)d_in[6];
    const float* kv_w1  = (const float*)d_in[7];
    const float* kv_w2  = (const float*)d_in[8];
    const float* qn_w   = (const float*)d_in[9];
    const float* qn_b   = (const float*)d_in[10];
    const float* kn_w   = (const float*)d_in[11];
    const float* kn_b   = (const float*)d_in[12];
    const float* phx_w1 = (const float*)d_in[13];
    const float* phx_w2 = (const float*)d_in[14];
    const float* phh_w1 = (const float*)d_in[15];
    const float* phh_b1 = (const float*)d_in[16];
    const float* phh_w2 = (const float*)d_in[17];
    const float* phh_b2 = (const float*)d_in[18];

    float* out  = (float*)d_out;
    float* Xout = out;
    float* Hout = out + BB * NN * 3;

    cudaFuncSetAttribute(se3_kernel, cudaFuncAttributeMaxDynamicSharedMemorySize,
                         (int)sizeof(Smem));

    se3_kernel<<<BB, NT, sizeof(Smem)>>>(X, Hg, xnw, q_w1, q_w2, kv_w1, kv_w2,
                                         qn_w, qn_b, kn_w, kn_b,
                                         phx_w1, phx_w2,
                                         phh_w1, phh_b1, phh_w2, phh_b2,
                                         Xout, Hout);
}